// round 2
// baseline (speedup 1.0000x reference)
#include <cuda_runtime.h>

// MWPT: 3-level wavelet packet transform, fully fused.
// x: [128,1,65536] f32, kernel: [1,1,8] f32.
// out = concat(level1 [128,2,32768], level2 [128,4,16384], level3 [128,8,8192])
// conv: out[n] = sum_k x[(2n + k - 3) mod L] * w[k]  (circular, stride 2)
// hi-pass QMF: w_hi[k] = (-1)^k * w_lo[7-k]
//
// R2 changes vs R1: tile halved (N3=512), s2 aliased onto sx (smem 98.7KB->33.2KB,
// occupancy 2 -> ~6 blocks/SM), 4-wide thread tiling with float4 smem loads and
// 128-bit global stores (smem instr count ~4x down).

namespace {
constexpr int T       = 65536;
constexpr int KS      = 8;
constexpr int N3      = 512;             // level-3 outputs per node per block
constexpr int N2C     = 1032;            // level-2 computed per node (1030 needed, pad to /4)
constexpr int N1C     = 2072;            // level-1 computed per node (2070 needed, pad to /4)
constexpr int NXP     = 4152;            // x samples staged (4150 needed)
constexpr int THREADS = 256;
constexpr int SMEM_FLOATS = NXP + 2 * N1C;     // 8296 floats; s2 (4*N2C=4128) aliases sx
constexpr int SMEM_BYTES  = SMEM_FLOATS * (int)sizeof(float);

constexpr long OUT1_BASE = 0;
constexpr long OUT2_BASE = 128L * 2 * 32768;
constexpr long OUT3_BASE = OUT2_BASE + 128L * 4 * 16384;
}

// Load 14 consecutive floats (covers 4 stride-2 windows of 8) starting at p
// (p must be 16B-aligned). 3x LDS.128 + 1x LDS.64.
__device__ __forceinline__ void load14(const float* p, float v[14]) {
    float4 A = *(const float4*)p;
    float4 B = *(const float4*)(p + 4);
    float4 C = *(const float4*)(p + 8);
    float2 D = *(const float2*)(p + 12);
    v[0]=A.x; v[1]=A.y; v[2]=A.z;  v[3]=A.w;
    v[4]=B.x; v[5]=B.y; v[6]=B.z;  v[7]=B.w;
    v[8]=C.x; v[9]=C.y; v[10]=C.z; v[11]=C.w;
    v[12]=D.x; v[13]=D.y;
}

__device__ __forceinline__ void qmf4(const float v[14], const float wlo[KS],
                                     const float whi[KS], float lo[4], float hi[4]) {
    #pragma unroll
    for (int j = 0; j < 4; ++j) { lo[j] = 0.f; hi[j] = 0.f; }
    #pragma unroll
    for (int j = 0; j < 4; ++j)
        #pragma unroll
        for (int k = 0; k < KS; ++k) {
            float t = v[2 * j + k];
            lo[j] += t * wlo[k];
            hi[j] += t * whi[k];
        }
}

__global__ __launch_bounds__(THREADS) void mwpt_kernel(
    const float* __restrict__ x,
    const float* __restrict__ kern,
    float* __restrict__ out)
{
    extern __shared__ float sm[];
    float* sx = sm;              // [NXP]   x slice
    float* s1 = sm + NXP;        // [2][N1C] level-1 (a0, a4)
    float* s2 = sm;              // [4][N2C] level-2 (b0,b2,b4,b6) — ALIASES sx

    const int b   = blockIdx.y;
    const int n0  = blockIdx.x * N3;
    const int tid = threadIdx.x;

    float wlo[KS], whi[KS];
    #pragma unroll
    for (int k = 0; k < KS; ++k) wlo[k] = __ldg(&kern[k]);
    #pragma unroll
    for (int k = 0; k < KS; ++k) whi[k] = (k & 1) ? -wlo[KS - 1 - k] : wlo[KS - 1 - k];

    // ---- Stage x with circular wrap (global base j0 = 8*n0 - 21) ----
    const float* xb = x + (size_t)b * T;
    const int j0 = 8 * n0 - 21;
    for (int i = tid; i < NXP; i += THREADS)
        sx[i] = xb[(j0 + i) & (T - 1)];
    __syncthreads();

    // ---- Level 1: 518 groups of 4 outputs, both QMF branches per read ----
    for (int g = tid; g < N1C / 4; g += THREADS) {
        float v[14], lo[4], hi[4];
        load14(sx + 8 * g, v);
        qmf4(v, wlo, whi, lo, hi);
        *(float4*)(s1 + 4 * g)       = make_float4(lo[0], lo[1], lo[2], lo[3]);
        *(float4*)(s1 + N1C + 4 * g) = make_float4(hi[0], hi[1], hi[2], hi[3]);
    }
    __syncthreads();

    // ---- Level-1 gmem writes: owned slice global [4n0,4n0+2048), local off 9 ----
    {
        float* o1 = out + OUT1_BASE + (size_t)b * (2 * 32768) + 4 * n0;
        for (int g = tid; g < N3; g += THREADS) {           // 512 float4 groups/node
            int s = 9 + 4 * g;
            *(float4*)(o1 + 4 * g) =
                make_float4(s1[s], s1[s + 1], s1[s + 2], s1[s + 3]);
            int h = N1C + s;
            *(float4*)(o1 + 32768 + 4 * g) =
                make_float4(s1[h], s1[h + 1], s1[h + 2], s1[h + 3]);
        }
    }

    // ---- Level 2: items = (group, parent); writes s2 (sx now dead) ----
    for (int t = tid; t < 2 * (N2C / 4); t += THREADS) {    // 516 items
        const int par = t & 1;
        const int g   = t >> 1;
        float v[14], lo[4], hi[4];
        load14(s1 + par * N1C + 8 * g, v);
        qmf4(v, wlo, whi, lo, hi);
        // parent 0 (a0) -> b0(q0), b2(q1); parent 1 (a4) -> b4(q2), b6(q3)
        *(float4*)(s2 + (2 * par)     * N2C + 4 * g) = make_float4(lo[0], lo[1], lo[2], lo[3]);
        *(float4*)(s2 + (2 * par + 1) * N2C + 4 * g) = make_float4(hi[0], hi[1], hi[2], hi[3]);
    }
    __syncthreads();

    // ---- Level-2 gmem writes: owned slice global [2n0,2n0+1024), local off 3 ----
    // s2 order [b0,b2,b4,b6] -> output node positions {0,1,3,2}
    {
        float* o2 = out + OUT2_BASE + (size_t)b * (4 * 16384) + 2 * n0;
        for (int g = tid; g < (2 * N3) / 4; g += THREADS) { // 256 float4 groups/node
            int s = 3 + 4 * g;
            #pragma unroll
            for (int q = 0; q < 4; ++q) {
                const int pos = (q == 0) ? 0 : (q == 1) ? 1 : (q == 2) ? 3 : 2;
                const float* src = s2 + q * N2C + s;
                *(float4*)(o2 + pos * 16384 + 4 * g) =
                    make_float4(src[0], src[1], src[2], src[3]);
            }
        }
    }

    // ---- Level 3: items = (group, parent); stream straight to gmem ----
    // s2[par]: b0,b2,b4,b6 -> children (c0,c1),(c2,c3),(c4,c5),(c6,c7)
    // output order [c0,c1,c3,c2,c6,c7,c5,c4] -> positions below
    {
        float* o3 = out + OUT3_BASE + (size_t)b * (8 * 8192) + n0;
        for (int t = tid; t < 4 * (N3 / 4); t += THREADS) { // 512 items
            const int par = t & 3;
            const int g   = t >> 2;
            float v[14], lo[4], hi[4];
            load14(s2 + par * N2C + 8 * g, v);
            qmf4(v, wlo, whi, lo, hi);
            const int pos_lo = (par == 0) ? 0 : (par == 1) ? 3 : (par == 2) ? 7 : 4;
            const int pos_hi = (par == 0) ? 1 : (par == 1) ? 2 : (par == 2) ? 6 : 5;
            *(float4*)(o3 + pos_lo * 8192 + 4 * g) = make_float4(lo[0], lo[1], lo[2], lo[3]);
            *(float4*)(o3 + pos_hi * 8192 + 4 * g) = make_float4(hi[0], hi[1], hi[2], hi[3]);
        }
    }
}

extern "C" void kernel_launch(void* const* d_in, const int* in_sizes, int n_in,
                              void* d_out, int out_size)
{
    const float* x    = (const float*)d_in[0];
    const float* kern = (const float*)d_in[1];
    float* out        = (float*)d_out;

    cudaFuncSetAttribute(mwpt_kernel,
                         cudaFuncAttributeMaxDynamicSharedMemorySize,
                         SMEM_BYTES);

    dim3 grid(8192 / N3, 128);   // 16 chunks x 128 batch rows = 2048 blocks
    mwpt_kernel<<<grid, THREADS, SMEM_BYTES>>>(x, kern, out);
}

// round 3
// speedup vs baseline: 1.2893x; 1.2893x over previous
#include <cuda_runtime.h>

// MWPT: 3-level wavelet packet transform, fully fused, polyphase (even/odd)
// shared-memory layout so every stride-2 conv read is a unit-stride float4.
//
// x: [128,1,65536] f32, kernel w: [1,1,8] f32.
// out = concat(level1 [128,2,32768], level2 [128,4,16384], level3 [128,8,8192])
// conv: out[n] = sum_k in[(2n + k - 3) mod L] * w[k]  (circular, stride 2)
// hi-pass QMF: whi[k] = (-1)^k * wlo[7-k]
// level2 node order [b0,b2,b6,b4]; level3 [c0,c1,c3,c2,c6,c7,c5,c4].
//
// Index algebra (per block, n0 = first owned level-3 index, j0 = 8n0-21 odd):
//  x staged split from x_hat[i] = x[j0-1+i]:  xE[i]=x_hat[2i], xO[i]=x_hat[2i+1]
//  a_{m'} (m' = m_global - 4n0 + 9) = sum_j xO[m'+j]wl[2j] + xE[m'+j+1]wl[2j+1]
//  a stored: aE[v]=a_{2v}, aO[v]=a_{2v+1}
//  b_q (q = l_global - 2n0)        = sum_j aE[q+3+j]w[2j] + aO[q+3+j]w[2j+1]
//  b stored: bE[v]=b_{2v-2}, bO[v]=b_{2v-3}
//  c_r (r = i_global - n0)         = sum_j bO[r+j]w[2j] + bE[r+j]w[2j+1]

namespace {
constexpr int T  = 65536, MSK = T - 1, KS = 8;
constexpr int N3 = 512;
constexpr int THREADS = 256;
constexpr int XSZ  = 2076;                 // xE/xO floats each
constexpr int ASZ  = 1036;                 // each of aE0,aO0,aE4,aO4
constexpr int BSZ  = 520;                  // each of 8 b arrays
constexpr int UNION0 = 4160;               // max(2*XSZ=4152, 8*BSZ=4160): b aliases x
constexpr int SMEM_FLOATS = UNION0 + 4 * ASZ;   // 8304
constexpr int SMEM_BYTES  = SMEM_FLOATS * 4;    // 33216
constexpr long OUT2_BASE = 128L * 2 * 32768;
constexpr long OUT3_BASE = OUT2_BASE + 128L * 4 * 16384;
}

__device__ __forceinline__ void ld8(const float* s, float v[8]) {
    float4 a = *(const float4*)s;       // base always ≡0 mod 4 floats
    float4 b = *(const float4*)(s + 4);
    v[0]=a.x; v[1]=a.y; v[2]=a.z; v[3]=a.w;
    v[4]=b.x; v[5]=b.y; v[6]=b.z; v[7]=b.w;
}

// lo[p] = sum_j A[p+j]*wl[2j] + B[p+j]*wl[2j+1]   (p=0..3), hi likewise
__device__ __forceinline__ void qmf4(const float* A, const float* B,
                                     const float wl[8], const float wh[8],
                                     float lo[4], float hi[4]) {
    #pragma unroll
    for (int p = 0; p < 4; ++p) {
        float l = 0.f, h = 0.f;
        #pragma unroll
        for (int j = 0; j < 4; ++j) {
            float a = A[p + j], b = B[p + j];
            l += a * wl[2*j] + b * wl[2*j+1];
            h += a * wh[2*j] + b * wh[2*j+1];
        }
        lo[p] = l; hi[p] = h;
    }
}

__global__ __launch_bounds__(THREADS) void mwpt_kernel(
    const float* __restrict__ x,
    const float* __restrict__ kern,
    float* __restrict__ out)
{
    extern __shared__ float sm[];
    float* xE = sm;                     // [XSZ]
    float* xO = sm + XSZ;               // [XSZ]
    // b arrays alias the x region (x dead after level-1 compute)
    float* bE[4], * bO[4];
    #pragma unroll
    for (int n = 0; n < 4; ++n) { bE[n] = sm + n * (2*BSZ); bO[n] = bE[n] + BSZ; }
    float* aE0 = sm + UNION0;
    float* aO0 = aE0 + ASZ;
    float* aE4 = aO0 + ASZ;
    float* aO4 = aE4 + ASZ;

    const int b   = blockIdx.y;
    const int n0  = blockIdx.x * N3;
    const int tid = threadIdx.x;

    float wl[KS], wh[KS];
    #pragma unroll
    for (int k = 0; k < KS; ++k) wl[k] = __ldg(&kern[k]);
    #pragma unroll
    for (int k = 0; k < KS; ++k) wh[k] = (k & 1) ? -wl[KS-1-k] : wl[KS-1-k];

    // ---- Stage x (aligned coalesced LDG.64, conflict-free scalar STS) ----
    {
        const int base = 8 * n0 - 22;   // j0-1, even
        for (int i = tid; i < XSZ; i += THREADS) {
            float2 v = *(const float2*)(x + (size_t)b * T + ((base + 2*i) & MSK));
            xE[i] = v.x; xO[i] = v.y;
        }
    }
    __syncthreads();

    // ---- Level 1: m' in [0,2072), 4 per thread-chunk ----
    for (int g = tid; g < 518; g += THREADS) {
        float e8[8], o8[8], lo[4], hi[4];
        ld8(xE + 4*g, e8);
        ld8(xO + 4*g, o8);
        qmf4(o8, e8 + 1, wl, wh, lo, hi);   // xO even taps, xE shifted +1 odd taps
        *(float2*)(aE0 + 2*g) = make_float2(lo[0], lo[2]);
        *(float2*)(aO0 + 2*g) = make_float2(lo[1], lo[3]);
        *(float2*)(aE4 + 2*g) = make_float2(hi[0], hi[2]);
        *(float2*)(aO4 + 2*g) = make_float2(hi[1], hi[3]);
    }
    __syncthreads();

    // ---- Level-1 owned gmem writes: a m' in [9, 2057) -> out1[4n0 ..) ----
    {
        float* o1 = out + (size_t)b * (2 * 32768) + 4 * n0;
        #pragma unroll
        for (int it = 0; it < 4; ++it) {
            const int node = it >> 1;
            const int u = ((it & 1) << 8) + tid;          // [0,512)
            const float* AE = node ? aE4 : aE0;
            const float* AO = node ? aO4 : aO0;
            float2 po  = *(const float2*)(AO + 4 + 2*u);  // aO[4+2u], aO[5+2u]
            float2 pe0 = *(const float2*)(AE + 4 + 2*u);  // _, aE[5+2u]
            float2 pe1 = *(const float2*)(AE + 6 + 2*u);  // aE[6+2u], _
            *(float4*)(o1 + node * 32768 + 4*u) =
                make_float4(po.x, pe0.y, po.y, pe1.x);
        }
    }

    // ---- Level 2: q in [-3, 1029), chunks of 4 (writes b over dead x) ----
    #pragma unroll
    for (int par = 0; par < 2; ++par) {
        const float* AE = par ? aE4 : aE0;
        const float* AO = par ? aO4 : aO0;
        for (int g = tid; g < 258; g += THREADS) {
            float e8[8], o8[8], lo[4], hi[4];
            ld8(AE + 4*g, e8);
            ld8(AO + 4*g, o8);
            qmf4(e8, o8, wl, wh, lo, hi);
            // chunk q = 4g-3+p: p=0->bO[2g], p=1->bE[2g], p=2->bO[2g+1], p=3->bE[2g+1]
            *(float2*)(bO[2*par]     + 2*g) = make_float2(lo[0], lo[2]);
            *(float2*)(bE[2*par]     + 2*g) = make_float2(lo[1], lo[3]);
            *(float2*)(bO[2*par + 1] + 2*g) = make_float2(hi[0], hi[2]);
            *(float2*)(bE[2*par + 1] + 2*g) = make_float2(hi[1], hi[3]);
        }
    }
    __syncthreads();

    // ---- Level-2 owned gmem writes: q in [0,1024) -> out2[2n0 ..) ----
    // storage [b0,b2,b4,b6] -> output positions {0,1,3,2}
    {
        float* o2 = out + OUT2_BASE + (size_t)b * (4 * 16384) + 2 * n0;
        #pragma unroll
        for (int node = 0; node < 4; ++node) {
            const int pos = (node == 0) ? 0 : (node == 1) ? 1 : (node == 2) ? 3 : 2;
            const int u = tid;                            // [0,256)
            float2 e0 = *(const float2*)(bE[node] + 2*u);      // _, bE[2u+1]
            float2 e1 = *(const float2*)(bE[node] + 2*u + 2);  // bE[2u+2], _
            float2 o0 = *(const float2*)(bO[node] + 2*u + 2);  // bO[2u+2], bO[2u+3]
            // q=4u..4u+3 -> {bE[2u+1], bO[2u+2], bE[2u+2], bO[2u+3]}
            *(float4*)(o2 + pos * 16384 + 4*u) =
                make_float4(e0.y, o0.x, e1.x, o0.y);
        }
    }

    // ---- Level 3: r in [0,512), stream to gmem ----
    // parent p -> children at output positions pos_lo={0,3,7,4}, pos_hi={1,2,6,5}
    {
        float* o3 = out + OUT3_BASE + (size_t)b * (8 * 8192) + n0;
        #pragma unroll
        for (int it = 0; it < 2; ++it) {
            const int t   = (it << 8) + tid;
            const int par = t >> 7;          // warp-uniform
            const int g   = t & 127;
            float e8[8], o8[8], lo[4], hi[4];
            ld8(bE[par] + 4*g, e8);
            ld8(bO[par] + 4*g, o8);
            qmf4(o8, e8, wl, wh, lo, hi);    // bO carries even taps, bE odd taps
            const int pos_lo = (par == 0) ? 0 : (par == 1) ? 3 : (par == 2) ? 7 : 4;
            const int pos_hi = (par == 0) ? 1 : (par == 1) ? 2 : (par == 2) ? 6 : 5;
            *(float4*)(o3 + pos_lo * 8192 + 4*g) = make_float4(lo[0], lo[1], lo[2], lo[3]);
            *(float4*)(o3 + pos_hi * 8192 + 4*g) = make_float4(hi[0], hi[1], hi[2], hi[3]);
        }
    }
}

extern "C" void kernel_launch(void* const* d_in, const int* in_sizes, int n_in,
                              void* d_out, int out_size)
{
    const float* x    = (const float*)d_in[0];
    const float* kern = (const float*)d_in[1];
    float* out        = (float*)d_out;

    cudaFuncSetAttribute(mwpt_kernel,
                         cudaFuncAttributeMaxDynamicSharedMemorySize,
                         SMEM_BYTES);

    dim3 grid(8192 / N3, 128);   // 16 x 128 = 2048 blocks
    mwpt_kernel<<<grid, THREADS, SMEM_BYTES>>>(x, kern, out);
}